// round 10
// baseline (speedup 1.0000x reference)
#include <cuda_runtime.h>
#include <cuda_fp16.h>
#include <cstdint>

// ============================================================
// MADE/IAF flow step on tensor cores via mma.sync (fp16 HMMA).
// Accuracy: 2-term fp16 split of the ACTIVATION operand only:
//   A ~= Ahi + Alo/2048 (Alo stored pre-scaled x2048), B = W fp16.
//   hi-term: f32-accumulate HMMA; lo-term: f16-accumulate HMMA
//   (scaled so products are fp16-normal), combined in epilogue.
// + MADE-mask block sparsity (exact k-chunk skipping, ~44%).
// R10: 64x128 CTA tiles (2048/1024 CTAs -> 6.9/3.5 waves, small tail)
//      + f16-acc lo-term MMA.
// GEMM1: h = relu(zp @ (W1*M1) + b1)   [4096,1024]x[1024,4096]
// GEMM2: res = h @ (W2*M2) + b2        [4096,4096]x[4096,2048]
// finish: x = zp*exp(log_s)+mu (inv-permuted), log_det = row-sum
// ============================================================

#define LO_SCALE   2048.0f
#define LO_ISCALE  4.8828125e-4f

// ---------------- device scratch (no allocs allowed) ----------------
__device__ float  g_res[4096ull * 2048ull];   // gemm2 out (fp32)
__device__ int    g_inv[4096];
__device__ __half g_zhi[4096ull * 1024ull], g_zlo[4096ull * 1024ull];  // [B,D] (lo x2048)
__device__ __half g_w1hi[4096ull * 1024ull];                           // [N=4096,K=1024]
__device__ __half g_hhi[4096ull * 4096ull], g_hlo[4096ull * 4096ull];  // [B,H] (lo x2048)
__device__ __half g_w2hi[2048ull * 4096ull];                           // [N=2048,K=4096]

// ---------------- PTX helpers (all baseline sm_80+ PTX) ----------------
__device__ __forceinline__ uint32_t smem_u32(const void* p) {
    uint32_t a;
    asm("{ .reg .u64 t; cvta.to.shared.u64 t, %1; cvt.u32.u64 %0, t; }" : "=r"(a) : "l"(p));
    return a;
}
__device__ __forceinline__ void cp16(uint32_t s, const void* g) {
    asm volatile("cp.async.cg.shared.global [%0], [%1], 16;" :: "r"(s), "l"(g));
}
__device__ __forceinline__ void cp_commit() {
    asm volatile("cp.async.commit_group;" ::: "memory");
}
__device__ __forceinline__ void cp_wait1() {
    asm volatile("cp.async.wait_group 1;" ::: "memory");
}
__device__ __forceinline__ void ldm_x4(uint32_t addr, uint32_t* r) {
    asm volatile("ldmatrix.sync.aligned.m8n8.x4.shared.b16 {%0,%1,%2,%3}, [%4];"
                 : "=r"(r[0]), "=r"(r[1]), "=r"(r[2]), "=r"(r[3]) : "r"(addr));
}
// f32-accumulate HMMA (hi term)
__device__ __forceinline__ void mma_f32(float* c, const uint32_t* a, const uint32_t* b) {
    asm volatile(
        "mma.sync.aligned.m16n8k16.row.col.f32.f16.f16.f32 "
        "{%0,%1,%2,%3}, {%4,%5,%6,%7}, {%8,%9}, {%0,%1,%2,%3};"
        : "+f"(c[0]), "+f"(c[1]), "+f"(c[2]), "+f"(c[3])
        : "r"(a[0]), "r"(a[1]), "r"(a[2]), "r"(a[3]), "r"(b[0]), "r"(b[1]));
}
// f16-accumulate HMMA (lo term; C/D = 2x f16x2 regs)
__device__ __forceinline__ void mma_f16(uint32_t* c, const uint32_t* a, const uint32_t* b) {
    asm volatile(
        "mma.sync.aligned.m16n8k16.row.col.f16.f16.f16.f16 "
        "{%0,%1}, {%2,%3,%4,%5}, {%6,%7}, {%0,%1};"
        : "+r"(c[0]), "+r"(c[1])
        : "r"(a[0]), "r"(a[1]), "r"(a[2]), "r"(a[3]), "r"(b[0]), "r"(b[1]));
}

// ---------------- prep kernels ----------------
__global__ void build_inv(const int* __restrict__ perm, int D) {
    int d = blockIdx.x * blockDim.x + threadIdx.x;
    if (d < D) g_inv[perm[d]] = d;
}

__global__ void split_z_kernel(const float* __restrict__ z, const int* __restrict__ perm,
                               int D, long total) {
    long idx = (long)blockIdx.x * blockDim.x + threadIdx.x;
    if (idx >= total) return;
    int i = (int)(idx >> 10);      // D = 1024
    int k = (int)(idx & 1023);
    float v = z[(size_t)i * D + perm[k]];
    __half hi = __float2half(v);
    __half lo = __float2half((v - __half2float(hi)) * LO_SCALE);
    g_zhi[idx] = hi;
    g_zlo[idx] = lo;
}

// mask+transpose to fp16: W [K,N] fp32 -> out [N,K] fp16.
// mode 1: mask = (n % 1023) >= k          (W1/M1)
// mode 2: mask = (n % 1024) > (k % 1023)  (W2/M2)
__global__ __launch_bounds__(256) void prep_w_kernel(
    const float* __restrict__ W, __half* __restrict__ oHi,
    int K, int N, int mode) {
    __shared__ float tile[64][65];
    const int n0 = blockIdx.x * 64;
    const int k0 = blockIdx.y * 64;
    const int tid = threadIdx.x;
#pragma unroll
    for (int it = 0; it < 4; it++) {
        int lin = tid + it * 256;
        int k = lin >> 4;
        int n4 = (lin & 15) << 2;
        float4 v = *reinterpret_cast<const float4*>(&W[(size_t)(k0 + k) * N + n0 + n4]);
        tile[k][n4 + 0] = v.x;
        tile[k][n4 + 1] = v.y;
        tile[k][n4 + 2] = v.z;
        tile[k][n4 + 3] = v.w;
    }
    __syncthreads();
    const int tn = tid & 63;
    const int kg = tid >> 6;
    const int n  = n0 + tn;
    const int jm = (mode == 1) ? (n % 1023) : (n & 1023);
    uint32_t hibuf[8];
#pragma unroll
    for (int e = 0; e < 8; e++) {
        float v0, v1;
        {
            int k = k0 + kg * 16 + 2 * e;
            float v = tile[kg * 16 + 2 * e][tn];
            bool m = (mode == 1) ? (jm >= k) : (jm > (k % 1023));
            v0 = m ? v : 0.f;
        }
        {
            int k = k0 + kg * 16 + 2 * e + 1;
            float v = tile[kg * 16 + 2 * e + 1][tn];
            bool m = (mode == 1) ? (jm >= k) : (jm > (k % 1023));
            v1 = m ? v : 0.f;
        }
        __half2 ph; ph.x = __float2half(v0); ph.y = __float2half(v1);
        hibuf[e] = *reinterpret_cast<uint32_t*>(&ph);
    }
    const size_t ob = (size_t)n * K + k0 + kg * 16;
    *reinterpret_cast<uint4*>(oHi + ob)     = *reinterpret_cast<uint4*>(hibuf);
    *reinterpret_cast<uint4*>(oHi + ob + 8) = *reinterpret_cast<uint4*>(hibuf + 4);
}

// ---------------- mma.sync GEMM ----------------
// C[m,n] = sum_k A[m,k]*B[n,k]; A [M,K] hi/lo fp16 (lo x2048), B [N,K] fp16.
// CTA tile 64x128, K-chunk 32, 4 warps (1x4 in N), warp tile 64x32,
// 3-stage cp.async. Smem rows 128B XOR-swizzled:
// byte = row*128 + (inner ^ ((row&7)<<4)). A rows: [0,64) hi, [64,128) lo.
#define SA_BYTES   8192
#define SB_BYTES   16384
#define STG_BYTES  (SA_BYTES + SB_BYTES)
#define SM_TOTAL   (3 * STG_BYTES + 1024)
#define NTHR       128

template <int MODE>
__global__ __launch_bounds__(NTHR) void gemm_mma(
    const __half* __restrict__ Ahi, const __half* __restrict__ Alo,
    const __half* __restrict__ Bhi,
    const float* __restrict__ bias, int K, int Nout,
    float* __restrict__ outF,
    __half* __restrict__ outHi, __half* __restrict__ outLo)
{
    extern __shared__ char smem[];
    const uint32_t sb = smem_u32(smem);
    int* kt = (int*)(smem + 3 * STG_BYTES);
    const int tid  = threadIdx.x;
    const int lane = tid & 31;
    const int wn   = tid >> 5;     // 4 warps in N
    const int row0 = blockIdx.y * 64;
    const int col0 = blockIdx.x * 128;
    const int nk   = K >> 5;

    // ---- kept-chunk list (mask-induced block sparsity) ----
    if (tid == 0) {
        int c = 0;
        for (int t = 0; t < nk; t++) {
            const int k0 = t << 5;
            bool keep;
            if (MODE == 1) {
                int c0 = col0 % 1023;
                int jmmax = (c0 + 127 > 1022) ? 1022 : (c0 + 127);
                keep = (k0 <= jmmax);
            } else {
                int km0 = k0 % 1023;
                int jdmax = (col0 & 1023) + 127;
                keep = (km0 < jdmax) || (km0 > 991);
            }
            if (keep) kt[c++] = t;
        }
        kt[255] = c;
    }
    __syncthreads();
    const int cnt = kt[255];

    float    accH[4][4][4];   // hi term, f32 acc
    uint32_t accL[4][4][2];   // lo term, f16x2 acc
#pragma unroll
    for (int mt = 0; mt < 4; mt++)
#pragma unroll
        for (int nt = 0; nt < 4; nt++) {
#pragma unroll
            for (int e = 0; e < 4; e++) accH[mt][nt][e] = 0.f;
            accL[mt][nt][0] = 0u;
            accL[mt][nt][1] = 0u;
        }

    auto load_stage = [&](int chunk, int slot) {
        const int k0 = chunk << 5;
        const uint32_t s0 = sb + slot * STG_BYTES;
        // A: 64 rows x (hi 64B + lo 64B) = 512 cp16
#pragma unroll
        for (int i = 0; i < 4; i++) {
            int idx = tid + i * NTHR;
            int row = idx >> 3, cc = idx & 7;
            const __half* src =
                ((cc < 4) ? Ahi : Alo) + (size_t)(row0 + row) * K + k0 + (cc & 3) * 8;
            cp16(s0 + row * 128 + ((cc * 16) ^ ((row & 7) << 4)), src);
        }
        // B: 128 rows x hi 64B = 512 cp16
#pragma unroll
        for (int i = 0; i < 4; i++) {
            int idx = tid + i * NTHR;
            int row = idx >> 2, cc = idx & 3;
            const __half* src = Bhi + (size_t)(col0 + row) * K + k0 + cc * 8;
            cp16(s0 + SA_BYTES + row * 128 + ((cc * 16) ^ ((row & 7) << 4)), src);
        }
    };

    load_stage(kt[0], 0);
    cp_commit();
    if (cnt > 1) load_stage(kt[1], 1);
    cp_commit();

    // fragment address components
    int rA[4], xA[4];
#pragma unroll
    for (int mt = 0; mt < 4; mt++) {
        int r = mt * 16 + (lane & 15);
        rA[mt] = r * 128;
        xA[mt] = (r & 7) << 4;
    }
    const int kA2 = (lane >> 4) << 4;
    int rB[2], xB[2];
#pragma unroll
    for (int p = 0; p < 2; p++) {
        int r = wn * 32 + p * 16 + (lane & 7) + ((lane & 16) >> 1);
        rB[p] = r * 128;
        xB[p] = (r & 7) << 4;
    }
    const int kB2 = (lane & 8) << 1;

    for (int i = 0; i < cnt; i++) {
        cp_wait1();
        __syncthreads();
        if (i + 2 < cnt) load_stage(kt[i + 2], (i + 2) % 3);
        cp_commit();

        const uint32_t sA = sb + (i % 3) * STG_BYTES;
        const uint32_t sB = sA + SA_BYTES;
#pragma unroll
        for (int ks = 0; ks < 2; ks++) {
            const int kbA = ks * 32 + kA2;
            const int kbB = ks * 32 + kB2;
            uint32_t Ah[4][4], Al[4][4], bh[2][4];
#pragma unroll
            for (int mt = 0; mt < 4; mt++)
                ldm_x4(sA + rA[mt] + (kbA ^ xA[mt]), Ah[mt]);
#pragma unroll
            for (int mt = 0; mt < 4; mt++)
                ldm_x4(sA + rA[mt] + ((64 + kbA) ^ xA[mt]), Al[mt]);
#pragma unroll
            for (int p = 0; p < 2; p++)
                ldm_x4(sB + rB[p] + (kbB ^ xB[p]), bh[p]);
            // hi term (f32 acc)
#pragma unroll
            for (int mt = 0; mt < 4; mt++)
#pragma unroll
                for (int p = 0; p < 2; p++) {
                    mma_f32(accH[mt][2 * p + 0], Ah[mt], bh[p]);
                    mma_f32(accH[mt][2 * p + 1], Ah[mt], bh[p] + 2);
                }
            // lo term (f16 acc, operand pre-scaled x2048)
#pragma unroll
            for (int mt = 0; mt < 4; mt++)
#pragma unroll
                for (int p = 0; p < 2; p++) {
                    mma_f16(accL[mt][2 * p + 0], Al[mt], bh[p]);
                    mma_f16(accL[mt][2 * p + 1], Al[mt], bh[p] + 2);
                }
        }
    }

    // epilogue: v = accH + accL/2048 + bias
    const int mrow = lane >> 2;
    const int mcol = (lane & 3) * 2;
#pragma unroll
    for (int mt = 0; mt < 4; mt++) {
        const int rbase = row0 + mt * 16 + mrow;
#pragma unroll
        for (int nt = 0; nt < 4; nt++) {
            const int c = col0 + wn * 32 + nt * 8 + mcol;
            const float b0 = bias[c], b1 = bias[c + 1];
#pragma unroll
            for (int h = 0; h < 2; h++) {
                const int r = rbase + h * 8;
                const __half2 lo2 = *reinterpret_cast<const __half2*>(&accL[mt][nt][h]);
                float v0 = accH[mt][nt][2 * h + 0] + LO_ISCALE * __half2float(lo2.x) + b0;
                float v1 = accH[mt][nt][2 * h + 1] + LO_ISCALE * __half2float(lo2.y) + b1;
                const size_t o = (size_t)r * Nout + c;
                if (MODE == 1) {
                    v0 = fmaxf(v0, 0.f);
                    v1 = fmaxf(v1, 0.f);
                    __half h0 = __float2half(v0);
                    __half h1 = __float2half(v1);
                    __half l0 = __float2half((v0 - __half2float(h0)) * LO_SCALE);
                    __half l1 = __float2half((v1 - __half2float(h1)) * LO_SCALE);
                    __half2 ph; ph.x = h0; ph.y = h1;
                    __half2 pl; pl.x = l0; pl.y = l1;
                    *(__half2*)(outHi + o) = ph;
                    *(__half2*)(outLo + o) = pl;
                } else {
                    *(float2*)(outF + o) = make_float2(v0, v1);
                }
            }
        }
    }
}

// ---------------- finish ----------------
__global__ void finish_kernel(const float* __restrict__ z,
                              const int* __restrict__ perm,
                              float* __restrict__ out,
                              int Bn, int D)
{
    const int i = blockIdx.x;
    const int t = threadIdx.x;
    __shared__ float red[256];

    const float* resrow = &g_res[(size_t)i * 2 * D];
    const float* zrow   = &z[(size_t)i * D];

    float s = 0.f;
    for (int d = t; d < D; d += blockDim.x) s += resrow[D + d];

    for (int j = t; j < D; j += blockDim.x) {
        int dj   = g_inv[j];
        float ls = resrow[D + dj];
        float mu = resrow[dj];
        float zp = zrow[perm[dj]];
        out[(size_t)i * D + j] = fmaf(zp, expf(ls), mu);
    }

    red[t] = s;
    __syncthreads();
    for (int off = 128; off > 0; off >>= 1) {
        if (t < off) red[t] += red[t + off];
        __syncthreads();
    }
    if (t == 0) out[(size_t)Bn * D + i] = red[0];
}

// ---------------- launch ----------------
extern "C" void kernel_launch(void* const* d_in, const int* in_sizes, int n_in,
                              void* d_out, int out_size) {
    const float* z    = (const float*)d_in[0];
    const float* W1   = (const float*)d_in[1];
    const float* b1   = (const float*)d_in[2];
    const float* W2   = (const float*)d_in[3];
    const float* b2   = (const float*)d_in[4];
    const int*   perm = (const int*)d_in[5];

    const int D  = in_sizes[5];      // 1024
    const int H  = in_sizes[2];      // 4096
    const int N2 = in_sizes[4];      // 2048
    const int B  = in_sizes[0] / D;  // 4096

    cudaFuncSetAttribute(gemm_mma<1>, cudaFuncAttributeMaxDynamicSharedMemorySize, SM_TOTAL);
    cudaFuncSetAttribute(gemm_mma<2>, cudaFuncAttributeMaxDynamicSharedMemorySize, SM_TOTAL);

    __half *zhi, *zlo, *w1hi, *hhi, *hlo, *w2hi;
    float* res;
    cudaGetSymbolAddress((void**)&zhi,  g_zhi);
    cudaGetSymbolAddress((void**)&zlo,  g_zlo);
    cudaGetSymbolAddress((void**)&w1hi, g_w1hi);
    cudaGetSymbolAddress((void**)&hhi,  g_hhi);
    cudaGetSymbolAddress((void**)&hlo,  g_hlo);
    cudaGetSymbolAddress((void**)&w2hi, g_w2hi);
    cudaGetSymbolAddress((void**)&res,  g_res);

    build_inv<<<(D + 255) / 256, 256>>>(perm, D);
    split_z_kernel<<<(long)B * D / 256, 256>>>(z, perm, D, (long)B * D);
    prep_w_kernel<<<dim3(H / 64, D / 64),  256>>>(W1, w1hi, D, H, 1);
    prep_w_kernel<<<dim3(N2 / 64, H / 64), 256>>>(W2, w2hi, H, N2, 2);

    // GEMM1: [B,D] x [D,H]^T-packed -> h (fp16 split)
    gemm_mma<1><<<dim3(H / 128, B / 64), NTHR, SM_TOTAL>>>(
        zhi, zlo, w1hi, b1, D, H, nullptr, hhi, hlo);
    // GEMM2: [B,H] x [H,2D]^T-packed -> res (fp32)
    gemm_mma<2><<<dim3(N2 / 128, B / 64), NTHR, SM_TOTAL>>>(
        hhi, hlo, w2hi, b2, H, N2, res, nullptr, nullptr);

    finish_kernel<<<B, 256>>>(z, perm, (float*)d_out, B, D);
}

// round 11
// speedup vs baseline: 2.6599x; 2.6599x over previous
#include <cuda_runtime.h>
#include <cuda_fp16.h>
#include <cstdint>

// ============================================================
// MADE/IAF flow step on tensor cores via mma.sync (fp16 HMMA, f32 acc).
// Single-pass fp16: A and B both fp16 (error ~ sqrt2 x the R8 split
// variant, ~4.3e-4 predicted, under the 1e-3 gate).
// + MADE-mask block sparsity (exact k-chunk skipping, ~44%).
// GEMM1: h = relu(zp @ (W1*M1) + b1)   [4096,1024]x[1024,4096]
// GEMM2: res = h @ (W2*M2) + b2        [4096,4096]x[4096,2048]
// finish: x = zp*exp(log_s)+mu (inv-permuted), log_det = row-sum
// ============================================================

// ---------------- device scratch (no allocs allowed) ----------------
__device__ float  g_res[4096ull * 2048ull];   // gemm2 out (fp32)
__device__ int    g_inv[4096];
__device__ __half g_zh[4096ull * 1024ull];    // [B,D] fp16
__device__ __half g_w1h[4096ull * 1024ull];   // [N=4096,K=1024]
__device__ __half g_hh[4096ull * 4096ull];    // [B,H] fp16
__device__ __half g_w2h[2048ull * 4096ull];   // [N=2048,K=4096]

// ---------------- PTX helpers (all baseline sm_80+ PTX) ----------------
__device__ __forceinline__ uint32_t smem_u32(const void* p) {
    uint32_t a;
    asm("{ .reg .u64 t; cvta.to.shared.u64 t, %1; cvt.u32.u64 %0, t; }" : "=r"(a) : "l"(p));
    return a;
}
__device__ __forceinline__ void cp16(uint32_t s, const void* g) {
    asm volatile("cp.async.cg.shared.global [%0], [%1], 16;" :: "r"(s), "l"(g));
}
__device__ __forceinline__ void cp_commit() {
    asm volatile("cp.async.commit_group;" ::: "memory");
}
__device__ __forceinline__ void cp_wait1() {
    asm volatile("cp.async.wait_group 1;" ::: "memory");
}
__device__ __forceinline__ void ldm_x4(uint32_t addr, uint32_t* r) {
    asm volatile("ldmatrix.sync.aligned.m8n8.x4.shared.b16 {%0,%1,%2,%3}, [%4];"
                 : "=r"(r[0]), "=r"(r[1]), "=r"(r[2]), "=r"(r[3]) : "r"(addr));
}
__device__ __forceinline__ void mma16816(float* c, const uint32_t* a, const uint32_t* b) {
    asm volatile(
        "mma.sync.aligned.m16n8k16.row.col.f32.f16.f16.f32 "
        "{%0,%1,%2,%3}, {%4,%5,%6,%7}, {%8,%9}, {%0,%1,%2,%3};"
        : "+f"(c[0]), "+f"(c[1]), "+f"(c[2]), "+f"(c[3])
        : "r"(a[0]), "r"(a[1]), "r"(a[2]), "r"(a[3]), "r"(b[0]), "r"(b[1]));
}

// ---------------- prep kernels ----------------
__global__ void build_inv(const int* __restrict__ perm, int D) {
    int d = blockIdx.x * blockDim.x + threadIdx.x;
    if (d < D) g_inv[perm[d]] = d;
}

__global__ void split_z_kernel(const float* __restrict__ z, const int* __restrict__ perm,
                               int D, long total) {
    long idx = (long)blockIdx.x * blockDim.x + threadIdx.x;
    if (idx >= total) return;
    int i = (int)(idx >> 10);      // D = 1024
    int k = (int)(idx & 1023);
    g_zh[idx] = __float2half(z[(size_t)i * D + perm[k]]);
}

// mask+transpose to fp16: W [K,N] fp32 -> out [N,K] fp16.
// mode 1: mask = (n % 1023) >= k          (W1/M1)
// mode 2: mask = (n % 1024) > (k % 1023)  (W2/M2)
__global__ __launch_bounds__(256) void prep_w_kernel(
    const float* __restrict__ W, __half* __restrict__ oH,
    int K, int N, int mode) {
    __shared__ float tile[64][65];
    const int n0 = blockIdx.x * 64;
    const int k0 = blockIdx.y * 64;
    const int tid = threadIdx.x;
#pragma unroll
    for (int it = 0; it < 4; it++) {
        int lin = tid + it * 256;          // 1024 float4 loads
        int k = lin >> 4;
        int n4 = (lin & 15) << 2;
        float4 v = *reinterpret_cast<const float4*>(&W[(size_t)(k0 + k) * N + n0 + n4]);
        tile[k][n4 + 0] = v.x;
        tile[k][n4 + 1] = v.y;
        tile[k][n4 + 2] = v.z;
        tile[k][n4 + 3] = v.w;
    }
    __syncthreads();
    const int tn = tid & 63;
    const int kg = tid >> 6;               // 0..3, 16 k each
    const int n  = n0 + tn;
    const int jm = (mode == 1) ? (n % 1023) : (n & 1023);
    uint32_t hibuf[8];
#pragma unroll
    for (int e = 0; e < 8; e++) {
        float v0, v1;
        {
            int k = k0 + kg * 16 + 2 * e;
            float v = tile[kg * 16 + 2 * e][tn];
            bool m = (mode == 1) ? (jm >= k) : (jm > (k % 1023));
            v0 = m ? v : 0.f;
        }
        {
            int k = k0 + kg * 16 + 2 * e + 1;
            float v = tile[kg * 16 + 2 * e + 1][tn];
            bool m = (mode == 1) ? (jm >= k) : (jm > (k % 1023));
            v1 = m ? v : 0.f;
        }
        __half2 ph; ph.x = __float2half(v0); ph.y = __float2half(v1);
        hibuf[e] = *reinterpret_cast<uint32_t*>(&ph);
    }
    const size_t ob = (size_t)n * K + k0 + kg * 16;
    *reinterpret_cast<uint4*>(oH + ob)     = *reinterpret_cast<uint4*>(hibuf);
    *reinterpret_cast<uint4*>(oH + ob + 8) = *reinterpret_cast<uint4*>(hibuf + 4);
}

// ---------------- mma.sync GEMM (single fp16, chunk skipping) ----------------
// C[m,n] = sum_k A[m,k]*B[n,k]; A [M,K] fp16, B [N,K] fp16.
// CTA tile 128x128, K-chunk 32, 4 warps (2x2), warp tile 64x64, 3-stage cp.async,
// 2 CTAs/SM. Smem rows 128B XOR-swizzled: byte = row*128 + (inner ^ ((row&7)<<4));
// only the k<64-byte (hi) slots of each row are used (A and B identical layout).
#define SA_BYTES   16384
#define STG_BYTES  32768
#define SM_TOTAL   (3 * STG_BYTES + 1024)
#define NTHR       128

template <int MODE>
__global__ __launch_bounds__(NTHR) void gemm_mma(
    const __half* __restrict__ Ah, const __half* __restrict__ Bh,
    const float* __restrict__ bias, int K, int Nout,
    float* __restrict__ outF, __half* __restrict__ outH)
{
    extern __shared__ char smem[];
    const uint32_t sb = smem_u32(smem);
    int* kt = (int*)(smem + 3 * STG_BYTES);
    const int tid  = threadIdx.x;
    const int lane = tid & 31;
    const int w    = tid >> 5;
    const int wm   = w & 1;        // 2 warps in M
    const int wn   = w >> 1;       // 2 warps in N
    const int row0 = blockIdx.y * 128;
    const int col0 = blockIdx.x * 128;
    const int nk   = K >> 5;

    // ---- build kept-chunk list (mask-induced block sparsity) ----
    if (tid == 0) {
        int c = 0;
        for (int t = 0; t < nk; t++) {
            const int k0 = t << 5;
            bool keep;
            if (MODE == 1) {
                int c0 = col0 % 1023;
                int jmmax = (c0 + 127 > 1022) ? 1022 : (c0 + 127);
                keep = (k0 <= jmmax);
            } else {
                int km0 = k0 % 1023;
                int jdmax = (col0 & 1023) + 127;
                keep = (km0 < jdmax) || (km0 > 991);
            }
            if (keep) kt[c++] = t;
        }
        kt[255] = c;
    }
    __syncthreads();
    const int cnt = kt[255];

    float acc[4][8][4];
#pragma unroll
    for (int mt = 0; mt < 4; mt++)
#pragma unroll
        for (int nt = 0; nt < 8; nt++)
#pragma unroll
            for (int e = 0; e < 4; e++) acc[mt][nt][e] = 0.f;

    auto load_stage = [&](int chunk, int slot) {
        const int k0 = chunk << 5;
        const uint32_t s0 = sb + slot * STG_BYTES;
        // A: 128 rows x 64B = 512 cp16
#pragma unroll
        for (int i = 0; i < 4; i++) {
            int idx = tid + i * NTHR;
            int row = idx >> 2, cc = idx & 3;
            const __half* src = Ah + (size_t)(row0 + row) * K + k0 + cc * 8;
            cp16(s0 + row * 128 + ((cc * 16) ^ ((row & 7) << 4)), src);
        }
        // B: 128 rows x 64B = 512 cp16
#pragma unroll
        for (int i = 0; i < 4; i++) {
            int idx = tid + i * NTHR;
            int row = idx >> 2, cc = idx & 3;
            const __half* src = Bh + (size_t)(col0 + row) * K + k0 + cc * 8;
            cp16(s0 + SA_BYTES + row * 128 + ((cc * 16) ^ ((row & 7) << 4)), src);
        }
    };

    load_stage(kt[0], 0);
    cp_commit();
    if (cnt > 1) load_stage(kt[1], 1);
    cp_commit();

    // fragment address components (per-thread constants)
    int rA[4], xA[4];
#pragma unroll
    for (int mt = 0; mt < 4; mt++) {
        int r = wm * 64 + mt * 16 + (lane & 15);
        rA[mt] = r * 128;
        xA[mt] = (r & 7) << 4;
    }
    const int kA2 = (lane >> 4) << 4;          // A k-byte offset part (0 or 16)
    int rB[4], xB[4];
#pragma unroll
    for (int p = 0; p < 4; p++) {
        int r = wn * 64 + p * 16 + (lane & 7) + ((lane & 16) >> 1);
        rB[p] = r * 128;
        xB[p] = (r & 7) << 4;
    }
    const int kB2 = (lane & 8) << 1;           // B k-byte offset part (0 or 16)

    for (int i = 0; i < cnt; i++) {
        cp_wait1();
        __syncthreads();
        if (i + 2 < cnt) load_stage(kt[i + 2], (i + 2) % 3);
        cp_commit();

        const uint32_t sA = sb + (i % 3) * STG_BYTES;
        const uint32_t sB = sA + SA_BYTES;
#pragma unroll
        for (int ks = 0; ks < 2; ks++) {
            const int kbA = ks * 32 + kA2;
            const int kbB = ks * 32 + kB2;
            uint32_t Af[4][4], bh[4][4];
#pragma unroll
            for (int mt = 0; mt < 4; mt++)
                ldm_x4(sA + rA[mt] + (kbA ^ xA[mt]), Af[mt]);
#pragma unroll
            for (int p = 0; p < 4; p++)
                ldm_x4(sB + rB[p] + (kbB ^ xB[p]), bh[p]);
#pragma unroll
            for (int mt = 0; mt < 4; mt++)
#pragma unroll
                for (int p = 0; p < 4; p++) {
                    mma16816(acc[mt][2 * p + 0], Af[mt], bh[p]);
                    mma16816(acc[mt][2 * p + 1], Af[mt], bh[p] + 2);
                }
        }
    }

    // epilogue
    const int mrow = lane >> 2;
    const int mcol = (lane & 3) * 2;
#pragma unroll
    for (int mt = 0; mt < 4; mt++) {
        const int rbase = row0 + wm * 64 + mt * 16 + mrow;
#pragma unroll
        for (int nt = 0; nt < 8; nt++) {
            const int c = col0 + wn * 64 + nt * 8 + mcol;
            const float b0 = bias[c], b1 = bias[c + 1];
#pragma unroll
            for (int h = 0; h < 2; h++) {
                const int r = rbase + h * 8;
                float v0 = acc[mt][nt][2 * h + 0] + b0;
                float v1 = acc[mt][nt][2 * h + 1] + b1;
                const size_t o = (size_t)r * Nout + c;
                if (MODE == 1) {
                    v0 = fmaxf(v0, 0.f);
                    v1 = fmaxf(v1, 0.f);
                    __half2 ph; ph.x = __float2half(v0); ph.y = __float2half(v1);
                    *(__half2*)(outH + o) = ph;
                } else {
                    *(float2*)(outF + o) = make_float2(v0, v1);
                }
            }
        }
    }
}

// ---------------- finish ----------------
__global__ void finish_kernel(const float* __restrict__ z,
                              const int* __restrict__ perm,
                              float* __restrict__ out,
                              int Bn, int D)
{
    const int i = blockIdx.x;
    const int t = threadIdx.x;
    __shared__ float red[256];

    const float* resrow = &g_res[(size_t)i * 2 * D];
    const float* zrow   = &z[(size_t)i * D];

    float s = 0.f;
    for (int d = t; d < D; d += blockDim.x) s += resrow[D + d];

    for (int j = t; j < D; j += blockDim.x) {
        int dj   = g_inv[j];
        float ls = resrow[D + dj];
        float mu = resrow[dj];
        float zp = zrow[perm[dj]];
        out[(size_t)i * D + j] = fmaf(zp, expf(ls), mu);
    }

    red[t] = s;
    __syncthreads();
    for (int off = 128; off > 0; off >>= 1) {
        if (t < off) red[t] += red[t + off];
        __syncthreads();
    }
    if (t == 0) out[(size_t)Bn * D + i] = red[0];
}

// ---------------- launch ----------------
extern "C" void kernel_launch(void* const* d_in, const int* in_sizes, int n_in,
                              void* d_out, int out_size) {
    const float* z    = (const float*)d_in[0];
    const float* W1   = (const float*)d_in[1];
    const float* b1   = (const float*)d_in[2];
    const float* W2   = (const float*)d_in[3];
    const float* b2   = (const float*)d_in[4];
    const int*   perm = (const int*)d_in[5];

    const int D  = in_sizes[5];      // 1024
    const int H  = in_sizes[2];      // 4096
    const int N2 = in_sizes[4];      // 2048
    const int B  = in_sizes[0] / D;  // 4096

    cudaFuncSetAttribute(gemm_mma<1>, cudaFuncAttributeMaxDynamicSharedMemorySize, SM_TOTAL);
    cudaFuncSetAttribute(gemm_mma<2>, cudaFuncAttributeMaxDynamicSharedMemorySize, SM_TOTAL);

    __half *zh, *w1h, *hh, *w2h;
    float* res;
    cudaGetSymbolAddress((void**)&zh,  g_zh);
    cudaGetSymbolAddress((void**)&w1h, g_w1h);
    cudaGetSymbolAddress((void**)&hh,  g_hh);
    cudaGetSymbolAddress((void**)&w2h, g_w2h);
    cudaGetSymbolAddress((void**)&res, g_res);

    build_inv<<<(D + 255) / 256, 256>>>(perm, D);
    split_z_kernel<<<(long)B * D / 256, 256>>>(z, perm, D, (long)B * D);
    prep_w_kernel<<<dim3(H / 64, D / 64),  256>>>(W1, w1h, D, H, 1);
    prep_w_kernel<<<dim3(N2 / 64, H / 64), 256>>>(W2, w2h, H, N2, 2);

    // GEMM1: [B,D] x [D,H]^T-packed -> h (fp16)
    gemm_mma<1><<<dim3(H / 128, B / 128), NTHR, SM_TOTAL>>>(
        zh, w1h, b1, D, H, nullptr, hh);
    // GEMM2: [B,H] x [H,2D]^T-packed -> res (fp32)
    gemm_mma<2><<<dim3(N2 / 128, B / 128), NTHR, SM_TOTAL>>>(
        hh, w2h, b2, H, N2, res, nullptr);

    finish_kernel<<<B, 256>>>(z, perm, (float*)d_out, B, D);
}

// round 12
// speedup vs baseline: 2.7480x; 1.0332x over previous
#include <cuda_runtime.h>
#include <cuda_fp16.h>
#include <cstdint>

// ============================================================
// MADE/IAF flow step on tensor cores via mma.sync (fp16 HMMA, f32 acc).
// Single-pass fp16 (rel_err ~4.4e-4, under the 1e-3 gate).
// + MADE-mask block sparsity (exact k-chunk skipping, ~44%).
// R12: overhead compression — merged prep launch; finish uses the
//      identity zp[i,inv[j]] == z[i,j] (direct coalesced z read) and
//      fuses the log_det row-sum into the same gather pass.
// GEMM1: h = relu(zp @ (W1*M1) + b1)   [4096,1024]x[1024,4096]
// GEMM2: res = h @ (W2*M2) + b2        [4096,4096]x[4096,2048]
// ============================================================

// ---------------- device scratch (no allocs allowed) ----------------
__device__ float  g_res[4096ull * 2048ull];   // gemm2 out (fp32)
__device__ int    g_inv[4096];
__device__ __half g_zh[4096ull * 1024ull];    // [B,D] fp16
__device__ __half g_w1h[4096ull * 1024ull];   // [N=4096,K=1024]
__device__ __half g_hh[4096ull * 4096ull];    // [B,H] fp16
__device__ __half g_w2h[2048ull * 4096ull];   // [N=2048,K=4096]

// ---------------- PTX helpers (all baseline sm_80+ PTX) ----------------
__device__ __forceinline__ uint32_t smem_u32(const void* p) {
    uint32_t a;
    asm("{ .reg .u64 t; cvta.to.shared.u64 t, %1; cvt.u32.u64 %0, t; }" : "=r"(a) : "l"(p));
    return a;
}
__device__ __forceinline__ void cp16(uint32_t s, const void* g) {
    asm volatile("cp.async.cg.shared.global [%0], [%1], 16;" :: "r"(s), "l"(g));
}
__device__ __forceinline__ void cp_commit() {
    asm volatile("cp.async.commit_group;" ::: "memory");
}
__device__ __forceinline__ void cp_wait1() {
    asm volatile("cp.async.wait_group 1;" ::: "memory");
}
__device__ __forceinline__ void ldm_x4(uint32_t addr, uint32_t* r) {
    asm volatile("ldmatrix.sync.aligned.m8n8.x4.shared.b16 {%0,%1,%2,%3}, [%4];"
                 : "=r"(r[0]), "=r"(r[1]), "=r"(r[2]), "=r"(r[3]) : "r"(addr));
}
__device__ __forceinline__ void mma16816(float* c, const uint32_t* a, const uint32_t* b) {
    asm volatile(
        "mma.sync.aligned.m16n8k16.row.col.f32.f16.f16.f32 "
        "{%0,%1,%2,%3}, {%4,%5,%6,%7}, {%8,%9}, {%0,%1,%2,%3};"
        : "+f"(c[0]), "+f"(c[1]), "+f"(c[2]), "+f"(c[3])
        : "r"(a[0]), "r"(a[1]), "r"(a[2]), "r"(a[3]), "r"(b[0]), "r"(b[1]));
}

// ---------------- prep kernels ----------------
__global__ void build_inv(const int* __restrict__ perm, int D) {
    int d = blockIdx.x * blockDim.x + threadIdx.x;
    if (d < D) g_inv[perm[d]] = d;
}

__global__ void split_z_kernel(const float* __restrict__ z, const int* __restrict__ perm,
                               int D, long total) {
    long idx = (long)blockIdx.x * blockDim.x + threadIdx.x;
    if (idx >= total) return;
    int i = (int)(idx >> 10);      // D = 1024
    int k = (int)(idx & 1023);
    g_zh[idx] = __float2half(z[(size_t)i * D + perm[k]]);
}

// Merged mask+transpose to fp16 for BOTH weights in one launch.
// W [K,N] fp32 -> out [N,K] fp16, 64x64 tiles.
// mode 1: mask = (n % 1023) >= k          (W1/M1)
// mode 2: mask = (n % 1024) > (k % 1023)  (W2/M2)
__global__ __launch_bounds__(256) void prep_w_all(
    const float* __restrict__ W1, const float* __restrict__ W2,
    __half* __restrict__ o1, __half* __restrict__ o2,
    int D, int H, int N2) {
    __shared__ float tile[64][65];
    const int nblk1 = (H / 64) * (D / 64);
    const int b = blockIdx.x;
    const float* W;
    __half* oH;
    int K, N, mode, tix;
    if (b < nblk1) { W = W1; oH = o1; K = D; N = H;  mode = 1; tix = b; }
    else           { W = W2; oH = o2; K = H; N = N2; mode = 2; tix = b - nblk1; }
    const int nx = N / 64;
    const int n0 = (tix % nx) * 64;
    const int k0 = (tix / nx) * 64;
    const int tid = threadIdx.x;
#pragma unroll
    for (int it = 0; it < 4; it++) {
        int lin = tid + it * 256;          // 1024 float4 loads
        int k = lin >> 4;
        int n4 = (lin & 15) << 2;
        float4 v = *reinterpret_cast<const float4*>(&W[(size_t)(k0 + k) * N + n0 + n4]);
        tile[k][n4 + 0] = v.x;
        tile[k][n4 + 1] = v.y;
        tile[k][n4 + 2] = v.z;
        tile[k][n4 + 3] = v.w;
    }
    __syncthreads();
    const int tn = tid & 63;
    const int kg = tid >> 6;               // 0..3, 16 k each
    const int n  = n0 + tn;
    const int jm = (mode == 1) ? (n % 1023) : (n & 1023);
    uint32_t hibuf[8];
#pragma unroll
    for (int e = 0; e < 8; e++) {
        float v0, v1;
        {
            int k = k0 + kg * 16 + 2 * e;
            float v = tile[kg * 16 + 2 * e][tn];
            bool m = (mode == 1) ? (jm >= k) : (jm > (k % 1023));
            v0 = m ? v : 0.f;
        }
        {
            int k = k0 + kg * 16 + 2 * e + 1;
            float v = tile[kg * 16 + 2 * e + 1][tn];
            bool m = (mode == 1) ? (jm >= k) : (jm > (k % 1023));
            v1 = m ? v : 0.f;
        }
        __half2 ph; ph.x = __float2half(v0); ph.y = __float2half(v1);
        hibuf[e] = *reinterpret_cast<uint32_t*>(&ph);
    }
    const size_t ob = (size_t)n * K + k0 + kg * 16;
    *reinterpret_cast<uint4*>(oH + ob)     = *reinterpret_cast<uint4*>(hibuf);
    *reinterpret_cast<uint4*>(oH + ob + 8) = *reinterpret_cast<uint4*>(hibuf + 4);
}

// ---------------- mma.sync GEMM (single fp16, chunk skipping) ----------------
// Identical to the validated R11 kernel.
#define SA_BYTES   16384
#define STG_BYTES  32768
#define SM_TOTAL   (3 * STG_BYTES + 1024)
#define NTHR       128

template <int MODE>
__global__ __launch_bounds__(NTHR) void gemm_mma(
    const __half* __restrict__ Ah, const __half* __restrict__ Bh,
    const float* __restrict__ bias, int K, int Nout,
    float* __restrict__ outF, __half* __restrict__ outH)
{
    extern __shared__ char smem[];
    const uint32_t sb = smem_u32(smem);
    int* kt = (int*)(smem + 3 * STG_BYTES);
    const int tid  = threadIdx.x;
    const int lane = tid & 31;
    const int w    = tid >> 5;
    const int wm   = w & 1;        // 2 warps in M
    const int wn   = w >> 1;       // 2 warps in N
    const int row0 = blockIdx.y * 128;
    const int col0 = blockIdx.x * 128;
    const int nk   = K >> 5;

    // ---- build kept-chunk list (mask-induced block sparsity) ----
    if (tid == 0) {
        int c = 0;
        for (int t = 0; t < nk; t++) {
            const int k0 = t << 5;
            bool keep;
            if (MODE == 1) {
                int c0 = col0 % 1023;
                int jmmax = (c0 + 127 > 1022) ? 1022 : (c0 + 127);
                keep = (k0 <= jmmax);
            } else {
                int km0 = k0 % 1023;
                int jdmax = (col0 & 1023) + 127;
                keep = (km0 < jdmax) || (km0 > 991);
            }
            if (keep) kt[c++] = t;
        }
        kt[255] = c;
    }
    __syncthreads();
    const int cnt = kt[255];

    float acc[4][8][4];
#pragma unroll
    for (int mt = 0; mt < 4; mt++)
#pragma unroll
        for (int nt = 0; nt < 8; nt++)
#pragma unroll
            for (int e = 0; e < 4; e++) acc[mt][nt][e] = 0.f;

    auto load_stage = [&](int chunk, int slot) {
        const int k0 = chunk << 5;
        const uint32_t s0 = sb + slot * STG_BYTES;
#pragma unroll
        for (int i = 0; i < 4; i++) {
            int idx = tid + i * NTHR;
            int row = idx >> 2, cc = idx & 3;
            const __half* src = Ah + (size_t)(row0 + row) * K + k0 + cc * 8;
            cp16(s0 + row * 128 + ((cc * 16) ^ ((row & 7) << 4)), src);
        }
#pragma unroll
        for (int i = 0; i < 4; i++) {
            int idx = tid + i * NTHR;
            int row = idx >> 2, cc = idx & 3;
            const __half* src = Bh + (size_t)(col0 + row) * K + k0 + cc * 8;
            cp16(s0 + SA_BYTES + row * 128 + ((cc * 16) ^ ((row & 7) << 4)), src);
        }
    };

    load_stage(kt[0], 0);
    cp_commit();
    if (cnt > 1) load_stage(kt[1], 1);
    cp_commit();

    int rA[4], xA[4];
#pragma unroll
    for (int mt = 0; mt < 4; mt++) {
        int r = wm * 64 + mt * 16 + (lane & 15);
        rA[mt] = r * 128;
        xA[mt] = (r & 7) << 4;
    }
    const int kA2 = (lane >> 4) << 4;
    int rB[4], xB[4];
#pragma unroll
    for (int p = 0; p < 4; p++) {
        int r = wn * 64 + p * 16 + (lane & 7) + ((lane & 16) >> 1);
        rB[p] = r * 128;
        xB[p] = (r & 7) << 4;
    }
    const int kB2 = (lane & 8) << 1;

    for (int i = 0; i < cnt; i++) {
        cp_wait1();
        __syncthreads();
        if (i + 2 < cnt) load_stage(kt[i + 2], (i + 2) % 3);
        cp_commit();

        const uint32_t sA = sb + (i % 3) * STG_BYTES;
        const uint32_t sB = sA + SA_BYTES;
#pragma unroll
        for (int ks = 0; ks < 2; ks++) {
            const int kbA = ks * 32 + kA2;
            const int kbB = ks * 32 + kB2;
            uint32_t Af[4][4], bh[4][4];
#pragma unroll
            for (int mt = 0; mt < 4; mt++)
                ldm_x4(sA + rA[mt] + (kbA ^ xA[mt]), Af[mt]);
#pragma unroll
            for (int p = 0; p < 4; p++)
                ldm_x4(sB + rB[p] + (kbB ^ xB[p]), bh[p]);
#pragma unroll
            for (int mt = 0; mt < 4; mt++)
#pragma unroll
                for (int p = 0; p < 4; p++) {
                    mma16816(acc[mt][2 * p + 0], Af[mt], bh[p]);
                    mma16816(acc[mt][2 * p + 1], Af[mt], bh[p] + 2);
                }
        }
    }

    const int mrow = lane >> 2;
    const int mcol = (lane & 3) * 2;
#pragma unroll
    for (int mt = 0; mt < 4; mt++) {
        const int rbase = row0 + wm * 64 + mt * 16 + mrow;
#pragma unroll
        for (int nt = 0; nt < 8; nt++) {
            const int c = col0 + wn * 64 + nt * 8 + mcol;
            const float b0 = bias[c], b1 = bias[c + 1];
#pragma unroll
            for (int h = 0; h < 2; h++) {
                const int r = rbase + h * 8;
                float v0 = acc[mt][nt][2 * h + 0] + b0;
                float v1 = acc[mt][nt][2 * h + 1] + b1;
                const size_t o = (size_t)r * Nout + c;
                if (MODE == 1) {
                    v0 = fmaxf(v0, 0.f);
                    v1 = fmaxf(v1, 0.f);
                    __half2 ph; ph.x = __float2half(v0); ph.y = __float2half(v1);
                    *(__half2*)(outH + o) = ph;
                } else {
                    *(float2*)(outF + o) = make_float2(v0, v1);
                }
            }
        }
    }
}

// ---------------- finish ----------------
// out[i,j] = z[i,j]*exp(ls[i,inv[j]]) + mu[i,inv[j]]   (zp[i,inv[j]] == z[i,j])
// log_det[i] = sum_j ls[i,inv[j]]  (= sum over all d; inv is a permutation)
__global__ __launch_bounds__(256) void finish_kernel(
    const float* __restrict__ z, float* __restrict__ out, int Bn, int D)
{
    __shared__ int   sinv[1024];
    __shared__ float red[256];
    const int t = threadIdx.x;
    for (int j = t; j < D; j += 256) sinv[j] = g_inv[j];
    __syncthreads();

#pragma unroll
    for (int r = 0; r < 2; r++) {
        const int i = blockIdx.x * 2 + r;
        const float* resrow = &g_res[(size_t)i * 2 * D];
        const float* zrow   = &z[(size_t)i * D];
        float s = 0.f;
        for (int j = t; j < D; j += 256) {
            int dj   = sinv[j];
            float ls = resrow[D + dj];
            float mu = resrow[dj];
            s += ls;
            out[(size_t)i * D + j] = fmaf(zrow[j], expf(ls), mu);
        }
        red[t] = s;
        __syncthreads();
        for (int off = 128; off > 0; off >>= 1) {
            if (t < off) red[t] += red[t + off];
            __syncthreads();
        }
        if (t == 0) out[(size_t)Bn * D + i] = red[0];
        __syncthreads();
    }
}

// ---------------- launch ----------------
extern "C" void kernel_launch(void* const* d_in, const int* in_sizes, int n_in,
                              void* d_out, int out_size) {
    const float* z    = (const float*)d_in[0];
    const float* W1   = (const float*)d_in[1];
    const float* b1   = (const float*)d_in[2];
    const float* W2   = (const float*)d_in[3];
    const float* b2   = (const float*)d_in[4];
    const int*   perm = (const int*)d_in[5];

    const int D  = in_sizes[5];      // 1024
    const int H  = in_sizes[2];      // 4096
    const int N2 = in_sizes[4];      // 2048
    const int B  = in_sizes[0] / D;  // 4096

    cudaFuncSetAttribute(gemm_mma<1>, cudaFuncAttributeMaxDynamicSharedMemorySize, SM_TOTAL);
    cudaFuncSetAttribute(gemm_mma<2>, cudaFuncAttributeMaxDynamicSharedMemorySize, SM_TOTAL);

    __half *zh, *w1h, *hh, *w2h;
    float* res;
    cudaGetSymbolAddress((void**)&zh,  g_zh);
    cudaGetSymbolAddress((void**)&w1h, g_w1h);
    cudaGetSymbolAddress((void**)&hh,  g_hh);
    cudaGetSymbolAddress((void**)&w2h, g_w2h);
    cudaGetSymbolAddress((void**)&res, g_res);

    build_inv<<<(D + 255) / 256, 256>>>(perm, D);
    split_z_kernel<<<(long)B * D / 256, 256>>>(z, perm, D, (long)B * D);
    const int nblk = (H / 64) * (D / 64) + (N2 / 64) * (H / 64);
    prep_w_all<<<nblk, 256>>>(W1, W2, w1h, w2h, D, H, N2);

    // GEMM1: [B,D] x [D,H]^T-packed -> h (fp16)
    gemm_mma<1><<<dim3(H / 128, B / 128), NTHR, SM_TOTAL>>>(
        zh, w1h, b1, D, H, nullptr, hh);
    // GEMM2: [B,H] x [H,2D]^T-packed -> res (fp32)
    gemm_mma<2><<<dim3(N2 / 128, B / 128), NTHR, SM_TOTAL>>>(
        hh, w2h, b2, H, N2, res, nullptr);

    finish_kernel<<<B / 2, 256>>>(z, (float*)d_out, B, D);
}